// round 17
// baseline (speedup 1.0000x reference)
#include <cuda_runtime.h>

typedef unsigned long long ull;

#define NQ 1024
#define NK 2048
#define DD 64
#define KSPLIT 16          // k-splits (NK/128)

// Scratch (static device globals — no allocation).
__device__ float g_qpT[DD * NQ];            // [h][q], b1 folded in
__device__ float g_kpT[DD * NK];            // [h][k]
__device__ ull   g_w2d[DD];                 // packed (w,w)
__device__ float g_ml[KSPLIT * NQ];         // slice-local max
__device__ float g_sl[KSPLIT * NQ];         // slice-local expsum
__device__ float g_part[KSPLIT * DD * NQ];  // pv partials [ks][d][q]

// ---- f32x2 helpers ----
__device__ __forceinline__ ull addx2(ull a, ull b) {
    ull d; asm("add.rn.f32x2 %0,%1,%2;" : "=l"(d) : "l"(a), "l"(b)); return d;
}
__device__ __forceinline__ ull fmax2(ull a, ull b, ull c) {
    ull d; asm("fma.rn.f32x2 %0,%1,%2,%3;" : "=l"(d) : "l"(a), "l"(b), "l"(c)); return d;
}
__device__ __forceinline__ ull packf2(float lo, float hi) {
    ull d; asm("mov.b64 %0,{%1,%2};" : "=l"(d)
               : "r"(__float_as_uint(lo)), "r"(__float_as_uint(hi))); return d;
}
__device__ __forceinline__ float2 unpackf2(ull x) {
    unsigned lo, hi; asm("mov.b64 {%0,%1},%2;" : "=r"(lo), "=r"(hi) : "l"(x));
    return make_float2(__uint_as_float(lo), __uint_as_float(hi));
}
__device__ __forceinline__ ull relu2(ull x) {
    float2 f = unpackf2(x);
    f.x = fmaxf(f.x, 0.f); f.y = fmaxf(f.y, 0.f);
    return packf2(f.x, f.y);
}

// ---------------------------------------------------------------------------
// Projection v3: no smem, no barriers. One h per warp, one column per lane.
// Grid = 96 col-tiles (32 q + 64 k) x 8 h-groups = 768 blocks, 256 threads.
// src reads: coalesced 128B per d; W1 row: warp-uniform (L1-resident).
// MLP = 64 loads in flight per thread -> latency fully hidden.
// ---------------------------------------------------------------------------
__global__ __launch_bounds__(256) void proj_kernel(
    const float* __restrict__ q_in, const float* __restrict__ k_in,
    const float* __restrict__ W1, const float* __restrict__ b1,
    const float* __restrict__ W2)
{
    const int t = threadIdx.x;
    const int bx = blockIdx.x;
    if (bx == 0 && t < 64) { float w = W2[t]; g_w2d[t] = packf2(w, w); }

    const int colTile = bx >> 3;             // 0..95
    const int hg = bx & 7;
    const int h = hg * 8 + (t >> 5);         // warp -> h
    const int lane = t & 31;

    const bool isQ = colTile < (NQ / 32);
    const float* src = isQ ? q_in : k_in;
    const int stride = isQ ? NQ : NK;
    const int c = (isQ ? colTile * 32 : (colTile - NQ / 32) * 32) + lane;
    const float* wrow = W1 + h * 128 + (isQ ? 0 : DD);
    float* dstT = isQ ? g_qpT : g_kpT;

    float acc0 = 0.f, acc1 = 0.f;
#pragma unroll
    for (int d = 0; d < 64; d += 2) {
        acc0 = fmaf(__ldg(wrow + d),     src[d * stride + c],       acc0);
        acc1 = fmaf(__ldg(wrow + d + 1), src[(d + 1) * stride + c], acc1);
    }
    float acc = acc0 + acc1;
    if (isQ) acc += b1[h];
    dstT[h * stride + c] = acc;
}

// ---------------------------------------------------------------------------
// Fused scores + softmax + PV-partial. Block = 32q x 128k. Grid 32*16 = 512.
// ---------------------------------------------------------------------------
__global__ __launch_bounds__(256) void fused_kernel(
    const float* __restrict__ value, const float* __restrict__ b2,
    float* __restrict__ scores)
{
    __shared__ __align__(16) char smbuf[49152];
    float* const qd = reinterpret_cast<float*>(smbuf);           // [64h][64] dup'd q
    float* const kp = reinterpret_cast<float*>(smbuf + 16384);   // [64h][128k]
    float* const Es = reinterpret_cast<float*>(smbuf);           // phase 2 [32q][128k]
    float* const Vs = reinterpret_cast<float*>(smbuf + 16384);   // phase 2 [64d][128k] swz

    const int t = threadIdx.x;
    const int qt = blockIdx.x >> 4, ks = blockIdx.x & 15;
    const int qb = qt * 32, kb = ks * 128;

    // ---- stage loads ----
#pragma unroll
    for (int r = 0; r < 8; ++r) {
        int i = t + 256 * r;                 // < 2048
        int h = i >> 5, qq = i & 31;
        float v = g_qpT[h * NQ + qb + qq];
        float2 dv = {v, v};
        *reinterpret_cast<float2*>(&qd[h * 64 + 2 * qq]) = dv;
    }
#pragma unroll
    for (int r = 0; r < 8; ++r) {
        int i = t + 256 * r;                 // float4 idx < 2048
        int h = i >> 5, c4 = (i & 31) * 4;
        *reinterpret_cast<float4*>(&kp[h * 128 + c4]) =
            *reinterpret_cast<const float4*>(&g_kpT[h * NK + kb + c4]);
    }
    __syncthreads();

    // ---- phase 1: MLP scores ----
    const int qg = t >> 5, kg = t & 31;      // warp == one qg
    const int q0 = 4 * qg, k0 = 4 * kg;

    ull acc[4][2];
#pragma unroll
    for (int i = 0; i < 4; ++i) { acc[i][0] = 0ULL; acc[i][1] = 0ULL; }

#pragma unroll 2
    for (int h2 = 0; h2 < 32; ++h2) {
        ulonglong2 w2p = *reinterpret_cast<const ulonglong2*>(&g_w2d[2 * h2]);
#pragma unroll
        for (int hh = 0; hh < 2; ++hh) {
            const int h = 2 * h2 + hh;
            const ull w2 = hh ? w2p.y : w2p.x;
            ulonglong2 kk_ = *reinterpret_cast<const ulonglong2*>(&kp[h * 128 + k0]);
            ulonglong2 qA = *reinterpret_cast<const ulonglong2*>(&qd[h * 64 + 8 * qg]);
            ulonglong2 qB = *reinterpret_cast<const ulonglong2*>(&qd[h * 64 + 8 * qg + 4]);
            acc[0][0] = fmax2(w2, relu2(addx2(qA.x, kk_.x)), acc[0][0]);
            acc[0][1] = fmax2(w2, relu2(addx2(qA.x, kk_.y)), acc[0][1]);
            acc[1][0] = fmax2(w2, relu2(addx2(qA.y, kk_.x)), acc[1][0]);
            acc[1][1] = fmax2(w2, relu2(addx2(qA.y, kk_.y)), acc[1][1]);
            acc[2][0] = fmax2(w2, relu2(addx2(qB.x, kk_.x)), acc[2][0]);
            acc[2][1] = fmax2(w2, relu2(addx2(qB.x, kk_.y)), acc[2][1]);
            acc[3][0] = fmax2(w2, relu2(addx2(qB.y, kk_.x)), acc[3][0]);
            acc[3][1] = fmax2(w2, relu2(addx2(qB.y, kk_.y)), acc[3][1]);
        }
    }

    const float b2v = b2[0];
    float s[4][4];
#pragma unroll
    for (int i = 0; i < 4; ++i) {
        float2 u0 = unpackf2(acc[i][0]);
        float2 u1 = unpackf2(acc[i][1]);
        s[i][0] = u0.x + b2v; s[i][1] = u0.y + b2v;
        s[i][2] = u1.x + b2v; s[i][3] = u1.y + b2v;
        float4 o = {s[i][0], s[i][1], s[i][2], s[i][3]};
        *reinterpret_cast<float4*>(&scores[(qb + q0 + i) * NK + kb + k0]) = o;
    }

    // row max (full-warp reductions; q0 uniform within warp)
    float mx[4];
#pragma unroll
    for (int i = 0; i < 4; ++i) {
        mx[i] = fmaxf(fmaxf(s[i][0], s[i][1]), fmaxf(s[i][2], s[i][3]));
#pragma unroll
        for (int off = 16; off; off >>= 1)
            mx[i] = fmaxf(mx[i], __shfl_xor_sync(0xffffffffu, mx[i], off));
    }
    // exp + row sum
    float e[4][4], sums[4];
#pragma unroll
    for (int i = 0; i < 4; ++i) {
        e[i][0] = __expf(s[i][0] - mx[i]); e[i][1] = __expf(s[i][1] - mx[i]);
        e[i][2] = __expf(s[i][2] - mx[i]); e[i][3] = __expf(s[i][3] - mx[i]);
        sums[i] = (e[i][0] + e[i][1]) + (e[i][2] + e[i][3]);
#pragma unroll
        for (int off = 16; off; off >>= 1)
            sums[i] += __shfl_xor_sync(0xffffffffu, sums[i], off);
    }
    if (kg == 0) {
#pragma unroll
        for (int i = 0; i < 4; ++i) {
            g_ml[ks * NQ + qb + q0 + i] = mx[i];
            g_sl[ks * NQ + qb + q0 + i] = sums[i];
        }
    }
    __syncthreads();                         // phase-1 smem now dead

    // ---- phase 2 staging: Es (exp'd) + Vs (swizzled) ----
#pragma unroll
    for (int i = 0; i < 4; ++i) {
        float4 o = {e[i][0], e[i][1], e[i][2], e[i][3]};
        *reinterpret_cast<float4*>(&Es[(q0 + i) * 128 + k0]) = o;
    }
#pragma unroll
    for (int r = 0; r < 8; ++r) {
        int i = t + 256 * r;                 // float4 idx < 2048
        int d = i >> 5, c4 = (i & 31) * 4;
        float4 v = *reinterpret_cast<const float4*>(&value[d * NK + kb + c4]);
        *reinterpret_cast<float4*>(&Vs[d * 128 + (c4 ^ ((d & 7) << 2))]) = v;
    }
    __syncthreads();

    // ---- GEMM: all 256 threads, 4q x 2d per thread, packed over k ----
    ull a2[4][2];
    const int dg = t & 31;
    const int q0b = 4 * (t >> 5);            // warp -> 4 q rows
    {
        const int xsw = (dg & 7) << 2;
        const float* VA = &Vs[dg * 128];
        const float* VB = &Vs[(dg + 32) * 128];
#pragma unroll
        for (int i = 0; i < 4; ++i) { a2[i][0] = 0ULL; a2[i][1] = 0ULL; }
#pragma unroll 4
        for (int kk = 0; kk < 32; ++kk) {
            const int kw = 4 * kk;
            const int kwx = kw ^ xsw;
            ulonglong2 v0 = *reinterpret_cast<const ulonglong2*>(&VA[kwx]);
            ulonglong2 v1 = *reinterpret_cast<const ulonglong2*>(&VB[kwx]);
#pragma unroll
            for (int i = 0; i < 4; ++i) {
                ulonglong2 ee = *reinterpret_cast<const ulonglong2*>(&Es[(q0b + i) * 128 + kw]);
                a2[i][0] = fmax2(ee.x, v0.x, a2[i][0]);
                a2[i][0] = fmax2(ee.y, v0.y, a2[i][0]);
                a2[i][1] = fmax2(ee.x, v1.x, a2[i][1]);
                a2[i][1] = fmax2(ee.y, v1.y, a2[i][1]);
            }
        }
    }
    __syncthreads();

    // ---- epilogue: transpose via smem (reuse Es region as [64][33]) ----
    float* EsT = Es;
#pragma unroll
    for (int i = 0; i < 4; ++i)
#pragma unroll
        for (int j = 0; j < 2; ++j) {
            float2 u = unpackf2(a2[i][j]);
            EsT[(dg + 32 * j) * 33 + q0b + i] = u.x + u.y;
        }
    __syncthreads();
#pragma unroll
    for (int r = 0; r < 8; ++r) {
        int i = t + 256 * r;                 // < 2048
        int d = i >> 5, qq = i & 31;
        g_part[ks * (DD * NQ) + d * NQ + qb + qq] = EsT[d * 33 + qq];
    }
}

// ---------------------------------------------------------------------------
// Reduce (+factor): block = 32 q-cols x 8 d-rows. Grid 32*8 = 256.
// ---------------------------------------------------------------------------
__global__ __launch_bounds__(256) void reduce_kernel(float* __restrict__ out)
{
    __shared__ float Fs[16 * 33];            // [s][32q] padded

    const int t = threadIdx.x;
    const int qb = (blockIdx.x & 31) * 32;
    const int d0 = (blockIdx.x >> 5) * 8;

#pragma unroll
    for (int r = 0; r < 2; ++r) {
        const int s = t & 15, qq = (t >> 4) + 16 * r;
        float ml = g_ml[s * NQ + qb + qq];
        float M = ml;
        M = fmaxf(M, __shfl_xor_sync(0xffffffffu, M, 8, 16));
        M = fmaxf(M, __shfl_xor_sync(0xffffffffu, M, 4, 16));
        M = fmaxf(M, __shfl_xor_sync(0xffffffffu, M, 2, 16));
        M = fmaxf(M, __shfl_xor_sync(0xffffffffu, M, 1, 16));
        float f = __expf(ml - M);
        float p = g_sl[s * NQ + qb + qq] * f;
        p += __shfl_xor_sync(0xffffffffu, p, 8, 16);
        p += __shfl_xor_sync(0xffffffffu, p, 4, 16);
        p += __shfl_xor_sync(0xffffffffu, p, 2, 16);
        p += __shfl_xor_sync(0xffffffffu, p, 1, 16);
        Fs[s * 33 + qq] = f / p;
    }
    __syncthreads();

    const int q = t & 31, dd = t >> 5;
    float o = 0.f;
#pragma unroll
    for (int ss = 0; ss < KSPLIT; ++ss)
        o = fmaf(g_part[ss * (DD * NQ) + (d0 + dd) * NQ + qb + q], Fs[ss * 33 + q], o);
    out[(d0 + dd) * NQ + qb + q] = o;
}

// ---------------------------------------------------------------------------
extern "C" void kernel_launch(void* const* d_in, const int* in_sizes, int n_in,
                              void* d_out, int out_size)
{
    const float* query = (const float*)d_in[0];   // [1,64,1024]
    const float* key   = (const float*)d_in[1];   // [1,64,2048]
    const float* value = (const float*)d_in[2];   // [1,64,2048]
    const float* W1    = (const float*)d_in[3];   // [64,128]
    const float* b1    = (const float*)d_in[4];   // [64]
    const float* W2    = (const float*)d_in[5];   // [1,64]
    const float* b2    = (const float*)d_in[6];   // [1]

    float* out    = (float*)d_out;                // [1,64,1024]
    float* scores = out + DD * NQ;                // [1,1024,2048]

    proj_kernel<<<((NQ + NK) / 32) * 8, 256>>>(query, key, W1, b1, W2);
    fused_kernel<<<(NQ / 32) * (NK / 128), 256>>>(value, b2, scores);
    reduce_kernel<<<(NQ / 32) * (DD / 8), 256>>>(out);
}